// round 9
// baseline (speedup 1.0000x reference)
#include <cuda_runtime.h>
#include <cuda_bf16.h>
#include <math.h>

#define B_ 8
#define N_ 2048
#define D_ 256
#define F_ 128
#define R_ 2
#define KQ 384            // D_+F_
#define M_TOT (B_*N_)     // 16384

typedef __nv_bfloat16 bf16;
typedef __nv_bfloat162 bf162;

// ---------------- scratch ----------------
__device__ float g_x1[B_*F_];
__device__ bf16  g_cat[(size_t)M_TOT*KQ];
__device__ bf16  g_q16[(size_t)M_TOT*D_];
__device__ bf16  g_k16[(size_t)B_*R_*N_*D_];
__device__ bf16  g_v16[(size_t)B_*R_*N_*D_];
__device__ bf16  g_h16[(size_t)M_TOT*R_*D_];
__device__ bf16  g_wq16[KQ*D_];
__device__ bf16  g_wk16[R_*KQ*D_];
__device__ bf16  g_wv16[R_*KQ*D_];
__device__ bf16  g_wf16[R_*D_*D_];

// ---------------- PTX helpers ----------------
__device__ __forceinline__ unsigned smem_u32(const void* p) {
    return (unsigned)__cvta_generic_to_shared(p);
}
#define LDSM_X4(r0,r1,r2,r3,addr) \
    asm volatile("ldmatrix.sync.aligned.m8n8.x4.shared.b16 {%0,%1,%2,%3}, [%4];" \
        : "=r"(r0),"=r"(r1),"=r"(r2),"=r"(r3) : "r"(addr))
#define LDSM_X4T(r0,r1,r2,r3,addr) \
    asm volatile("ldmatrix.sync.aligned.m8n8.x4.trans.shared.b16 {%0,%1,%2,%3}, [%4];" \
        : "=r"(r0),"=r"(r1),"=r"(r2),"=r"(r3) : "r"(addr))
#define LDSM_X2T(r0,r1,addr) \
    asm volatile("ldmatrix.sync.aligned.m8n8.x2.trans.shared.b16 {%0,%1}, [%2];" \
        : "=r"(r0),"=r"(r1) : "r"(addr))
#define MMA16816(c,a0,a1,a2,a3,b0,b1) \
    asm volatile("mma.sync.aligned.m16n8k16.row.col.f32.bf16.bf16.f32 " \
        "{%0,%1,%2,%3},{%4,%5,%6,%7},{%8,%9},{%0,%1,%2,%3};" \
        : "+f"(c[0]),"+f"(c[1]),"+f"(c[2]),"+f"(c[3]) \
        : "r"(a0),"r"(a1),"r"(a2),"r"(a3),"r"(b0),"r"(b1))
#define CPA16(s,g) asm volatile("cp.async.cg.shared.global [%0], [%1], 16;" :: "r"(s), "l"(g))
#define CPA_COMMIT() asm volatile("cp.async.commit_group;" ::: "memory")
#define CPA_WAIT0() asm volatile("cp.async.wait_group 0;" ::: "memory")

static __device__ __forceinline__ unsigned pk2(float a, float b) {
    bf162 t = __float22bfloat162_rn(make_float2(a, b));
    return *(unsigned*)&t;
}

// ---------------- x1 ----------------
__global__ void k_x1(const float* __restrict__ input_x,
                     const float* __restrict__ Ww,
                     const float* __restrict__ Wb) {
    __shared__ float row[F_];
    int b = blockIdx.x, j = threadIdx.x;
    row[j] = input_x[b*F_ + j];
    __syncthreads();
    float s = Wb[j];
    #pragma unroll 4
    for (int c = 0; c < F_; c++) s = fmaf(row[c], Ww[c*F_ + j], s);
    g_x1[b*F_ + j] = s;
}

// ---------------- concat ----------------
__global__ void k_cat(const float* __restrict__ node_embed) {
    int row = blockIdx.x;
    int col2 = threadIdx.x * 2;
    float2 v;
    if (col2 < D_) v = *(const float2*)(node_embed + (size_t)row*D_ + col2);
    else           v = *(const float2*)(g_x1 + (size_t)(row >> 11)*F_ + (col2 - D_));
    *(bf162*)(g_cat + (size_t)row*KQ + col2) = __float22bfloat162_rn(v);
}

// ---------------- weights to bf16 ----------------
__global__ void k_cvtw(const float* __restrict__ wq, const float* __restrict__ wk,
                       const float* __restrict__ wv, const float* __restrict__ wf) {
    int i = blockIdx.x * blockDim.x + threadIdx.x;
    int e = i * 2;
    const int SQ = KQ*D_, SK = R_*KQ*D_, SF = R_*D_*D_;
    if (e < SQ) {
        *(bf162*)(g_wq16 + e) = __float22bfloat162_rn(*(const float2*)(wq + e));
    } else if (e < SQ + SK) {
        int o = e - SQ;
        *(bf162*)(g_wk16 + o) = __float22bfloat162_rn(*(const float2*)(wk + o));
    } else if (e < SQ + 2*SK) {
        int o = e - SQ - SK;
        *(bf162*)(g_wv16 + o) = __float22bfloat162_rn(*(const float2*)(wv + o));
    } else if (e < SQ + 2*SK + SF) {
        int o = e - SQ - 2*SK;
        *(bf162*)(g_wf16 + o) = __float22bfloat162_rn(*(const float2*)(wf + o));
    }
}

// ============ qkv GEMM: CTA 128x256, 8 warps of 64x64 ============
// chunk 0: WQ -> q; 1,2: WK r0,r1 -> k; 3,4: WV r0,r1 -> v
__global__ void __launch_bounds__(256) k_qkv16(
        const float* __restrict__ WQ_b, const float* __restrict__ WK_b,
        const float* __restrict__ WV_b) {
    __shared__ bf16 As[128*40];       // [m][k32] pad 40
    __shared__ bf16 Bs[32*264];       // [k32][n256] pad 264
    int tid = threadIdx.x;
    int l = tid & 31, warp = tid >> 5;
    int warp_m = warp & 1, warp_n = warp >> 1;   // 2m x 4n, warp 64x64
    int quad = l >> 2, qlane = l & 3;

    int chunk = blockIdx.x;           // 0..4
    int m0 = blockIdx.y * 128;

    const bf16* Wg; const float* bias;
    if (chunk == 0)      { Wg = g_wq16;                           bias = WQ_b; }
    else if (chunk <= 2) { Wg = g_wk16 + (size_t)(chunk-1)*KQ*D_; bias = WK_b + (chunk-1)*D_; }
    else                 { Wg = g_wv16 + (size_t)(chunk-3)*KQ*D_; bias = WV_b + (chunk-3)*D_; }

    float acc[4][8][4];
    #pragma unroll
    for (int i=0;i<4;i++) for (int j=0;j<8;j++) for (int c=0;c<4;c++) acc[i][j][c]=0.f;

    int a_row = tid >> 2, a_seg = tid & 3;       // +256: row+64
    int b_seg = tid & 31;                        // B: row = it*8 + warp

    int arow = (l & 7) + ((l >> 3) & 1) * 8;
    int acol = (l >> 4) * 8;
    unsigned a_base = smem_u32(As) + (unsigned)(((warp_m*64 + arow)*40 + acol) * 2);
    int lt = l & 15;
    unsigned b_base = smem_u32(Bs) + (unsigned)((lt*264 + warp_n*64) * 2);

    {
        #pragma unroll
        for (int it=0; it<2; it++) {
            int r = a_row + it*64;
            *(uint4*)&As[r*40 + a_seg*8] =
                *(const uint4*)(g_cat + (size_t)(m0+r)*KQ + a_seg*8);
        }
        #pragma unroll
        for (int it=0; it<4; it++) {
            int rb = it*8 + warp;
            *(uint4*)&Bs[rb*264 + b_seg*8] =
                *(const uint4*)(Wg + (size_t)rb*D_ + b_seg*8);
        }
    }
    __syncthreads();

    for (int c0 = 0; c0 < KQ; c0 += 32) {
        bool nxt = (c0 + 32 < KQ);
        uint4 pa0, pa1, pb[4];
        if (nxt) {
            pa0 = *(const uint4*)(g_cat + (size_t)(m0+a_row   )*KQ + c0+32 + a_seg*8);
            pa1 = *(const uint4*)(g_cat + (size_t)(m0+a_row+64)*KQ + c0+32 + a_seg*8);
            #pragma unroll
            for (int it=0; it<4; it++)
                pb[it] = *(const uint4*)(Wg + (size_t)(c0+32 + it*8 + warp)*D_ + b_seg*8);
        }
        #pragma unroll
        for (int ks = 0; ks < 2; ks++) {
            unsigned bfr[8][2];
            #pragma unroll
            for (int nt=0; nt<8; nt++) {
                unsigned addr = b_base + (unsigned)((ks*16*264 + nt*8) * 2);
                LDSM_X2T(bfr[nt][0], bfr[nt][1], addr);
            }
            #pragma unroll
            for (int mt=0; mt<4; mt++) {
                unsigned a0,a1,a2,a3;
                unsigned addr = a_base + (unsigned)((mt*16*40 + ks*16) * 2);
                LDSM_X4(a0,a1,a2,a3, addr);
                #pragma unroll
                for (int nt=0; nt<8; nt++)
                    MMA16816(acc[mt][nt], a0,a1,a2,a3, bfr[nt][0], bfr[nt][1]);
            }
        }
        __syncthreads();
        if (nxt) {
            *(uint4*)&As[(a_row   )*40 + a_seg*8] = pa0;
            *(uint4*)&As[(a_row+64)*40 + a_seg*8] = pa1;
            #pragma unroll
            for (int it=0; it<4; it++)
                *(uint4*)&Bs[(it*8+warp)*264 + b_seg*8] = pb[it];
            __syncthreads();
        }
    }

    #pragma unroll
    for (int mt=0; mt<4; mt++) {
        #pragma unroll
        for (int half=0; half<2; half++) {
            int i = m0 + warp_m*64 + mt*16 + quad + half*8;
            int bb = i >> 11, ntok = i & (N_-1);
            #pragma unroll
            for (int nt=0; nt<8; nt++) {
                int jj = warp_n*64 + nt*8 + qlane*2;
                float2 bv = *(const float2*)(bias + jj);
                float v0 = acc[mt][nt][half*2+0] + bv.x;
                float v1 = acc[mt][nt][half*2+1] + bv.y;
                bf16* dst;
                if (chunk == 0)      dst = g_q16 + (size_t)i*D_ + jj;
                else if (chunk <= 2) dst = g_k16 + ((size_t)(bb*R_ + (chunk-1))*N_ + ntok)*D_ + jj;
                else                 dst = g_v16 + ((size_t)(bb*R_ + (chunk-3))*N_ + ntok)*D_ + jj;
                *(bf162*)dst = __float22bfloat162_rn(make_float2(v0, v1));
            }
        }
    }
}

// ============ fused attention, 256 threads = 8 warps ============
// S phase:  wm = warp&3 (m32 rows), wd = warp>>2 (kv-half of 32)
// PV phase: same wm (m32 rows), wd = d-half of 128
// smem: q[128][264] | K 2x[64][264] | V 2x[64][264] | P[128][72] | rs[2][128]
#define SM_Q   0
#define SM_K   67584
#define SM_V   135168
#define SM_P   202752
#define SM_RS  221184
#define SM_TOT 222208
#define NTILE  (N_/64)

__global__ void __launch_bounds__(256, 1) k_attn(const int* __restrict__ adj) {
    extern __shared__ char dsm[];
    unsigned sbase = smem_u32(dsm);
    int tid = threadIdx.x;
    int l = tid & 31, warp = tid >> 5;   // 8 warps
    int wm = warp & 3, wd = warp >> 2;
    int quad = l >> 2, qlane = l & 3;

    int m0 = blockIdx.x * 128;
    int p  = blockIdx.y;

    const bf16* gq = g_q16 + ((size_t)(p >> 1)*N_ + m0)*D_;
    const bf16* gk = g_k16 + (size_t)p*N_*D_;
    const bf16* gv = g_v16 + (size_t)p*N_*D_;

    // adj int2 pointers for the 4 row-groups (mt, half); tile stride = 32 int2
    const int2* ar[2][2];
    #pragma unroll
    for (int mt = 0; mt < 2; mt++)
        #pragma unroll
        for (int h = 0; h < 2; h++)
            ar[mt][h] = (const int2*)(adj +
                ((size_t)p*N_ + m0 + wm*32 + mt*16 + h*8 + quad)*N_ + wd*32) + qlane;

    // ---- preload q (128x256) + tile 0 K,V ----
    {
        #pragma unroll
        for (int it = 0; it < 16; it++) {
            int c = it*256 + tid;
            int row = c >> 5, seg = c & 31;
            CPA16(sbase + SM_Q + (unsigned)(row*528 + seg*16),
                  gq + (size_t)row*D_ + seg*8);
        }
        #pragma unroll
        for (int it = 0; it < 8; it++) {
            int c = it*256 + tid;
            int row = c >> 5, seg = c & 31;
            CPA16(sbase + SM_K + (unsigned)(row*528 + seg*16),
                  gk + (size_t)row*D_ + seg*8);
            CPA16(sbase + SM_V + (unsigned)(row*528 + seg*16),
                  gv + (size_t)row*D_ + seg*8);
        }
        CPA_COMMIT();
    }

    float o[2][16][4];
    #pragma unroll
    for (int m=0;m<2;m++)
        #pragma unroll
        for (int i=0;i<16;i++)
            { o[m][i][0]=0.f;o[m][i][1]=0.f;o[m][i][2]=0.f;o[m][i][3]=0.f; }
    float rs[2][2] = {{0.f,0.f},{0.f,0.f}};

    unsigned qa = sbase + SM_Q +
        (unsigned)(((wm*32 + (l & 7) + ((l >> 3) & 1)*8)*264 + (l >> 4)*8) * 2);
    unsigned kb = (unsigned)(((wd*32 + (l & 7) + ((l >> 4) & 1)*8)*264 + ((l >> 3) & 1)*8) * 2);
    unsigned pa = sbase + SM_P +
        (unsigned)(((wm*32 + (l & 7) + ((l >> 3) & 1)*8)*72 + (l >> 4)*8) * 2);
    unsigned vb = (unsigned)(((l & 15)*264 + wd*128 + ((l >> 4) & 1)*8) * 2);

    bf16* Psm = (bf16*)(dsm + SM_P);
    float* rsm = (float*)(dsm + SM_RS);

    for (int t = 0; t < NTILE; t++) {
        int buf = t & 1;
        CPA_WAIT0();
        __syncthreads();
        if (t + 1 < NTILE) {
            const bf16* gk1 = gk + (size_t)(t+1)*64*D_;
            const bf16* gv1 = gv + (size_t)(t+1)*64*D_;
            unsigned kd = sbase + SM_K + (unsigned)((buf^1))*33792u;
            unsigned vd = sbase + SM_V + (unsigned)((buf^1))*33792u;
            #pragma unroll
            for (int it = 0; it < 8; it++) {
                int c = it*256 + tid;
                int row = c >> 5, seg = c & 31;
                CPA16(kd + (unsigned)(row*528 + seg*16), gk1 + (size_t)row*D_ + seg*8);
                CPA16(vd + (unsigned)(row*528 + seg*16), gv1 + (size_t)row*D_ + seg*8);
            }
            CPA_COMMIT();
        }

        // ---- prefetch adj words (consumed after S MMAs) ----
        int2 am[2][2][4];
        #pragma unroll
        for (int mt = 0; mt < 2; mt++)
            #pragma unroll
            for (int h = 0; h < 2; h++)
                #pragma unroll
                for (int nt = 0; nt < 4; nt++)
                    am[mt][h][nt] = ar[mt][h][t*32 + nt*4];

        // ---- S = q @ K^T : warp m32 x kv32, k=256 ----
        unsigned kbb = sbase + SM_K + (unsigned)buf*33792u + kb;
        float sc[2][4][4];
        #pragma unroll
        for (int m=0;m<2;m++)
            #pragma unroll
            for (int i=0;i<4;i++)
                {sc[m][i][0]=0.f;sc[m][i][1]=0.f;sc[m][i][2]=0.f;sc[m][i][3]=0.f;}
        #pragma unroll
        for (int ks = 0; ks < 16; ks++) {
            unsigned b0,b1,b2,b3,b4,b5,b6,b7;
            LDSM_X4(b0,b1,b2,b3, kbb + (unsigned)((0*16*264 + ks*16) * 2));
            LDSM_X4(b4,b5,b6,b7, kbb + (unsigned)((1*16*264 + ks*16) * 2));
            #pragma unroll
            for (int mt = 0; mt < 2; mt++) {
                unsigned a0,a1,a2,a3;
                LDSM_X4(a0,a1,a2,a3, qa + (unsigned)((mt*16*264 + ks*16) * 2));
                MMA16816(sc[mt][0], a0,a1,a2,a3, b0,b1);
                MMA16816(sc[mt][1], a0,a1,a2,a3, b2,b3);
                MMA16816(sc[mt][2], a0,a1,a2,a3, b4,b5);
                MMA16816(sc[mt][3], a0,a1,a2,a3, b6,b7);
            }
        }

        // ---- mask + exp + rowsum + P to smem ----
        #pragma unroll
        for (int mt = 0; mt < 2; mt++) {
            int r0 = wm*32 + mt*16 + quad;
            #pragma unroll
            for (int nt = 0; nt < 4; nt++) {
                float e00 = am[mt][0][nt].x ? __expf(sc[mt][nt][0]*0.0625f) : 0.f;
                float e01 = am[mt][0][nt].y ? __expf(sc[mt][nt][1]*0.0625f) : 0.f;
                float e10 = am[mt][1][nt].x ? __expf(sc[mt][nt][2]*0.0625f) : 0.f;
                float e11 = am[mt][1][nt].y ? __expf(sc[mt][nt][3]*0.0625f) : 0.f;
                rs[mt][0] += e00 + e01;
                rs[mt][1] += e10 + e11;
                int col = wd*32 + nt*8 + qlane*2;
                *(unsigned*)(Psm + r0*72 + col)     = pk2(e00, e01);
                *(unsigned*)(Psm + (r0+8)*72 + col) = pk2(e10, e11);
            }
        }
        __syncthreads();

        // ---- O += P @ V : warp m32 x d128, k = kv64 ----
        unsigned vbb = sbase + SM_V + (unsigned)buf*33792u + vb;
        #pragma unroll
        for (int ks2 = 0; ks2 < 4; ks2++) {
            unsigned vB[8][4];
            #pragma unroll
            for (int nt16 = 0; nt16 < 8; nt16++)
                LDSM_X4T(vB[nt16][0],vB[nt16][1],vB[nt16][2],vB[nt16][3],
                         vbb + (unsigned)((ks2*16*264 + nt16*16) * 2));
            #pragma unroll
            for (int mt = 0; mt < 2; mt++) {
                unsigned a0,a1,a2,a3;
                LDSM_X4(a0,a1,a2,a3, pa + (unsigned)((mt*16*72 + ks2*16) * 2));
                #pragma unroll
                for (int nt16 = 0; nt16 < 8; nt16++) {
                    MMA16816(o[mt][nt16*2  ], a0,a1,a2,a3, vB[nt16][0], vB[nt16][1]);
                    MMA16816(o[mt][nt16*2+1], a0,a1,a2,a3, vB[nt16][2], vB[nt16][3]);
                }
            }
        }
    }

    // ---- rowsum reduce across qlane, publish per wd-half ----
    #pragma unroll
    for (int mt = 0; mt < 2; mt++)
        #pragma unroll
        for (int h = 0; h < 2; h++) {
            float v = rs[mt][h];
            v += __shfl_xor_sync(0xffffffffu, v, 1);
            v += __shfl_xor_sync(0xffffffffu, v, 2);
            if (qlane == 0)
                rsm[wd*128 + wm*32 + mt*16 + h*8 + quad] = v;
        }
    __syncthreads();

    // ---- normalize + write ----
    #pragma unroll
    for (int mt = 0; mt < 2; mt++) {
        int r = wm*32 + mt*16 + quad;
        float ta = rsm[r]     + rsm[128 + r];
        float tb = rsm[r + 8] + rsm[128 + r + 8];
        float ia = ta > 0.f ? __fdividef(1.f, ta) : 0.f;
        float ib = tb > 0.f ? __fdividef(1.f, tb) : 0.f;
        bf16* d0 = g_h16 + ((size_t)((p >> 1)*N_ + m0 + r))*(R_*D_) + (p & 1)*D_ + wd*128;
        bf16* d1 = d0 + (size_t)8*(R_*D_);
        #pragma unroll
        for (int nt = 0; nt < 16; nt++) {
            int col = nt*8 + qlane*2;
            *(unsigned*)(d0 + col) = pk2(o[mt][nt][0]*ia, o[mt][nt][1]*ia);
            *(unsigned*)(d1 + col) = pk2(o[mt][nt][2]*ib, o[mt][nt][3]*ib);
        }
    }
}

// ============ h_fused GEMM + relu + residual + LN (mma.sync, proven) ============
__global__ void __launch_bounds__(256) k_fused16(
        const float* __restrict__ node_embed,
        const float* __restrict__ WF_b,
        const float* __restrict__ ln_g, const float* __restrict__ ln_b,
        float* __restrict__ out) {
    __shared__ bf16 As[64*40];
    __shared__ bf16 Bs[32*264];
    __shared__ float2 part[64][4];
    int tid = threadIdx.x;
    int l = tid & 31, warp = tid >> 5;
    int warp_m = warp & 1, warp_n = warp >> 1;
    int quad = l >> 2, qlane = l & 3;
    int m0 = blockIdx.x * 64;

    float acc[2][8][4];
    #pragma unroll
    for (int i=0;i<2;i++) for (int j=0;j<8;j++) for (int c=0;c<4;c++) acc[i][j][c]=0.f;

    int a_row = tid >> 2, a_seg = tid & 3;
    int b_row = tid >> 5, b_seg = tid & 31;

    int arow = (l & 7) + ((l >> 3) & 1) * 8;
    int acol = (l >> 4) * 8;
    unsigned a_base = smem_u32(As) + (unsigned)(((warp_m*32 + arow)*40 + acol) * 2);
    int lt = l & 15;
    unsigned b_base = smem_u32(Bs) + (unsigned)((lt*264 + warp_n*64) * 2);

    {
        *(uint4*)&As[a_row*40 + a_seg*8] =
            *(const uint4*)(g_h16 + (size_t)(m0+a_row)*(R_*D_) + a_seg*8);
        #pragma unroll
        for (int it=0; it<4; it++) {
            int rb = b_row + it*8;
            *(uint4*)&Bs[rb*264 + b_seg*8] =
                *(const uint4*)(g_wf16 + (size_t)rb*D_ + b_seg*8);
        }
    }
    __syncthreads();

    for (int c0 = 0; c0 < R_*D_; c0 += 32) {
        bool nxt = (c0 + 32 < R_*D_);
        uint4 pa0, pb[4];
        if (nxt) {
            pa0 = *(const uint4*)(g_h16 + (size_t)(m0+a_row)*(R_*D_) + c0+32 + a_seg*8);
            #pragma unroll
            for (int it=0; it<4; it++)
                pb[it] = *(const uint4*)(g_wf16 + (size_t)(c0+32+b_row+it*8)*D_ + b_seg*8);
        }
        #pragma unroll
        for (int ks = 0; ks < 2; ks++) {
            unsigned a0,a1,a2,a3;
            unsigned bfr[8][2];
            #pragma unroll
            for (int nt=0; nt<8; nt++) {
                unsigned addr = b_base + (unsigned)((ks*16*264 + nt*8) * 2);
                LDSM_X2T(bfr[nt][0], bfr[nt][1], addr);
            }
            #pragma unroll
            for (int mt=0; mt<2; mt++) {
                unsigned addr = a_base + (unsigned)((mt*16*40 + ks*16) * 2);
                LDSM_X4(a0,a1,a2,a3, addr);
                #pragma unroll
                for (int nt=0; nt<8; nt++)
                    MMA16816(acc[mt][nt], a0,a1,a2,a3, bfr[nt][0], bfr[nt][1]);
            }
        }
        __syncthreads();
        if (nxt) {
            *(uint4*)&As[a_row*40 + a_seg*8] = pa0;
            #pragma unroll
            for (int it=0; it<4; it++)
                *(uint4*)&Bs[(b_row+it*8)*264 + b_seg*8] = pb[it];
            __syncthreads();
        }
    }

    #pragma unroll
    for (int mt=0; mt<2; mt++) {
        #pragma unroll
        for (int half=0; half<2; half++) {
            int row_l = warp_m*32 + mt*16 + quad + half*8;
            int grow = m0 + row_l;
            float s = 0.f, sq = 0.f;
            #pragma unroll
            for (int nt=0; nt<8; nt++) {
                int col = warp_n*64 + nt*8 + qlane*2;
                float2 bb = *(const float2*)(WF_b + col);
                float h0 = acc[mt][nt][half*2+0] + bb.x; h0 = h0 > 0.f ? h0 : 0.f;
                float h1 = acc[mt][nt][half*2+1] + bb.y; h1 = h1 > 0.f ? h1 : 0.f;
                float2 ne = *(const float2*)(node_embed + (size_t)grow*D_ + col);
                float y0 = ne.x + h0, y1 = ne.y + h1;
                acc[mt][nt][half*2+0] = y0;
                acc[mt][nt][half*2+1] = y1;
                s += y0 + y1;
                sq = fmaf(y0, y0, fmaf(y1, y1, sq));
            }
            s  += __shfl_xor_sync(0xffffffffu, s, 1);
            s  += __shfl_xor_sync(0xffffffffu, s, 2);
            sq += __shfl_xor_sync(0xffffffffu, sq, 1);
            sq += __shfl_xor_sync(0xffffffffu, sq, 2);
            if (qlane == 0) part[row_l][warp_n] = make_float2(s, sq);
        }
    }
    __syncthreads();
    #pragma unroll
    for (int mt=0; mt<2; mt++) {
        #pragma unroll
        for (int half=0; half<2; half++) {
            int row_l = warp_m*32 + mt*16 + quad + half*8;
            int grow = m0 + row_l;
            float s = 0.f, sq = 0.f;
            #pragma unroll
            for (int w=0; w<4; w++) { float2 pp = part[row_l][w]; s += pp.x; sq += pp.y; }
            float mu = s * (1.0f/256.0f);
            float var = sq * (1.0f/256.0f) - mu*mu;
            float rstd = rsqrtf(var + 1e-5f);
            #pragma unroll
            for (int nt=0; nt<8; nt++) {
                int col = warp_n*64 + nt*8 + qlane*2;
                float2 gg = *(const float2*)(ln_g + col);
                float2 bb = *(const float2*)(ln_b + col);
                float y0 = acc[mt][nt][half*2+0];
                float y1 = acc[mt][nt][half*2+1];
                float2 o;
                o.x = (y0 - mu) * rstd * gg.x + bb.x;
                o.y = (y1 - mu) * rstd * gg.y + bb.y;
                *(float2*)(out + (size_t)grow*D_ + col) = o;
            }
        }
    }
}

// ---------------- launch ----------------
extern "C" void kernel_launch(void* const* d_in, const int* in_sizes, int n_in,
                              void* d_out, int out_size) {
    const float* node_embed = (const float*)d_in[0];
    const float* input_x    = (const float*)d_in[1];
    const int*   adj        = (const int*)  d_in[2];
    const float* WQi_w      = (const float*)d_in[3];
    const float* WQi_b      = (const float*)d_in[4];
    const float* WQ_w       = (const float*)d_in[5];
    const float* WQ_b       = (const float*)d_in[6];
    const float* WK_w       = (const float*)d_in[7];
    const float* WK_b       = (const float*)d_in[8];
    const float* WV_w       = (const float*)d_in[9];
    const float* WV_b       = (const float*)d_in[10];
    const float* WF_w       = (const float*)d_in[11];
    const float* WF_b       = (const float*)d_in[12];
    const float* ln_g       = (const float*)d_in[13];
    const float* ln_b       = (const float*)d_in[14];
    float* out = (float*)d_out;

    cudaFuncSetAttribute(k_attn, cudaFuncAttributeMaxDynamicSharedMemorySize, SM_TOT);

    k_x1      <<<B_, F_>>>(input_x, WQi_w, WQi_b);
    k_cat     <<<M_TOT, 192>>>(node_embed);
    k_cvtw    <<<1216, 256>>>(WQ_w, WK_w, WV_w, WF_w);
    k_qkv16   <<<dim3(5, 128), 256>>>(WQ_b, WK_b, WV_b);
    k_attn    <<<dim3(16, B_*R_), 256, SM_TOT>>>(adj);
    k_fused16 <<<M_TOT/64, 256>>>(node_embed, WF_b, ln_g, ln_b, out);
}

// round 10
// speedup vs baseline: 1.5994x; 1.5994x over previous
#include <cuda_runtime.h>
#include <cuda_bf16.h>
#include <math.h>

#define B_ 8
#define N_ 2048
#define D_ 256
#define F_ 128
#define R_ 2
#define KQ 384            // D_+F_
#define M_TOT (B_*N_)     // 16384

typedef __nv_bfloat16 bf16;
typedef __nv_bfloat162 bf162;

// ---------------- scratch ----------------
__device__ float g_x1[B_*F_];
__device__ bf16  g_q16[(size_t)M_TOT*D_];
__device__ bf16  g_k16[(size_t)B_*R_*N_*D_];
__device__ bf16  g_v16[(size_t)B_*R_*N_*D_];
__device__ bf16  g_h16[(size_t)M_TOT*R_*D_];
__device__ bf16  g_wq16[KQ*D_];
__device__ bf16  g_wk16[R_*KQ*D_];
__device__ bf16  g_wv16[R_*KQ*D_];
__device__ bf16  g_wf16[R_*D_*D_];

// ---------------- PTX helpers ----------------
__device__ __forceinline__ unsigned smem_u32(const void* p) {
    return (unsigned)__cvta_generic_to_shared(p);
}
#define LDSM_X4(r0,r1,r2,r3,addr) \
    asm volatile("ldmatrix.sync.aligned.m8n8.x4.shared.b16 {%0,%1,%2,%3}, [%4];" \
        : "=r"(r0),"=r"(r1),"=r"(r2),"=r"(r3) : "r"(addr))
#define LDSM_X4T(r0,r1,r2,r3,addr) \
    asm volatile("ldmatrix.sync.aligned.m8n8.x4.trans.shared.b16 {%0,%1,%2,%3}, [%4];" \
        : "=r"(r0),"=r"(r1),"=r"(r2),"=r"(r3) : "r"(addr))
#define LDSM_X2T(r0,r1,addr) \
    asm volatile("ldmatrix.sync.aligned.m8n8.x2.trans.shared.b16 {%0,%1}, [%2];" \
        : "=r"(r0),"=r"(r1) : "r"(addr))
#define MMA16816(c,a0,a1,a2,a3,b0,b1) \
    asm volatile("mma.sync.aligned.m16n8k16.row.col.f32.bf16.bf16.f32 " \
        "{%0,%1,%2,%3},{%4,%5,%6,%7},{%8,%9},{%0,%1,%2,%3};" \
        : "+f"(c[0]),"+f"(c[1]),"+f"(c[2]),"+f"(c[3]) \
        : "r"(a0),"r"(a1),"r"(a2),"r"(a3),"r"(b0),"r"(b1))
#define CPA16(s,g) asm volatile("cp.async.cg.shared.global [%0], [%1], 16;" :: "r"(s), "l"(g))
#define CPA_COMMIT() asm volatile("cp.async.commit_group;" ::: "memory")
#define CPA_WAIT0() asm volatile("cp.async.wait_group 0;" ::: "memory")

static __device__ __forceinline__ unsigned pk2(float a, float b) {
    bf162 t = __float22bfloat162_rn(make_float2(a, b));
    return *(unsigned*)&t;
}

// ---------------- x1 ----------------
__global__ void k_x1(const float* __restrict__ input_x,
                     const float* __restrict__ Ww,
                     const float* __restrict__ Wb) {
    __shared__ float row[F_];
    int b = blockIdx.x, j = threadIdx.x;
    row[j] = input_x[b*F_ + j];
    __syncthreads();
    float s = Wb[j];
    #pragma unroll 4
    for (int c = 0; c < F_; c++) s = fmaf(row[c], Ww[c*F_ + j], s);
    g_x1[b*F_ + j] = s;
}

// ---------------- weights to bf16 ----------------
__global__ void k_cvtw(const float* __restrict__ wq, const float* __restrict__ wk,
                       const float* __restrict__ wv, const float* __restrict__ wf) {
    int i = blockIdx.x * blockDim.x + threadIdx.x;
    int e = i * 2;
    const int SQ = KQ*D_, SK = R_*KQ*D_, SF = R_*D_*D_;
    if (e < SQ) {
        *(bf162*)(g_wq16 + e) = __float22bfloat162_rn(*(const float2*)(wq + e));
    } else if (e < SQ + SK) {
        int o = e - SQ;
        *(bf162*)(g_wk16 + o) = __float22bfloat162_rn(*(const float2*)(wk + o));
    } else if (e < SQ + 2*SK) {
        int o = e - SQ - SK;
        *(bf162*)(g_wv16 + o) = __float22bfloat162_rn(*(const float2*)(wv + o));
    } else if (e < SQ + 2*SK + SF) {
        int o = e - SQ - 2*SK;
        *(bf162*)(g_wf16 + o) = __float22bfloat162_rn(*(const float2*)(wf + o));
    }
}

// inline concat loader: 8 bf16 of [node_embed | x1] row m, cols c..c+7
__device__ __forceinline__ uint4 load_cat8(const float* __restrict__ ne, int m, int c) {
    float4 f0, f1;
    if (c < D_) {
        const float* p = ne + (size_t)m*D_ + c;
        f0 = *(const float4*)p; f1 = *(const float4*)(p + 4);
    } else {
        const float* p = g_x1 + (size_t)(m >> 11)*F_ + (c - D_);
        f0 = *(const float4*)p; f1 = *(const float4*)(p + 4);
    }
    uint4 r;
    r.x = pk2(f0.x, f0.y); r.y = pk2(f0.z, f0.w);
    r.z = pk2(f1.x, f1.y); r.w = pk2(f1.z, f1.w);
    return r;
}

// ============ qkv GEMM (R7-proven shape: CTA 128x128, 8 warps 64x32) ============
__global__ void __launch_bounds__(256) k_qkv16(
        const float* __restrict__ node_embed,
        const float* __restrict__ WQ_b, const float* __restrict__ WK_b,
        const float* __restrict__ WV_b) {
    __shared__ bf16 As[128*40];
    __shared__ bf16 Bs[32*136];
    int tid = threadIdx.x;
    int l = tid & 31, warp = tid >> 5;
    int warp_m = warp & 1, warp_n = warp >> 1;
    int quad = l >> 2, qlane = l & 3;

    int bn = blockIdx.x;
    int m0 = blockIdx.y * 128;
    int chunk = bn >> 1;
    int j0 = (bn & 1) * 128;

    const bf16* Wg; const float* bias;
    if (chunk == 0)      { Wg = g_wq16;                           bias = WQ_b; }
    else if (chunk <= 2) { Wg = g_wk16 + (size_t)(chunk-1)*KQ*D_; bias = WK_b + (chunk-1)*D_; }
    else                 { Wg = g_wv16 + (size_t)(chunk-3)*KQ*D_; bias = WV_b + (chunk-3)*D_; }

    float acc[4][4][4];
    #pragma unroll
    for (int i=0;i<4;i++) for (int j=0;j<4;j++) for (int c=0;c<4;c++) acc[i][j][c]=0.f;

    int a_row = tid >> 2, a_seg = tid & 3;
    int b_row = tid >> 4, b_seg = tid & 15;

    int arow = (l & 7) + ((l >> 3) & 1) * 8;
    int acol = (l >> 4) * 8;
    unsigned a_base = smem_u32(As) + (unsigned)(((warp_m*64 + arow)*40 + acol) * 2);
    int lt = l & 15;
    unsigned b_base = smem_u32(Bs) + (unsigned)((lt*136 + warp_n*32) * 2);

    {
        #pragma unroll
        for (int it=0; it<2; it++) {
            int r = a_row + it*64;
            *(uint4*)&As[r*40 + a_seg*8] = load_cat8(node_embed, m0 + r, a_seg*8);
            int rb = b_row + it*16;
            *(uint4*)&Bs[rb*136 + b_seg*8] =
                *(const uint4*)(Wg + (size_t)rb*D_ + j0 + b_seg*8);
        }
    }
    __syncthreads();

    for (int c0 = 0; c0 < KQ; c0 += 32) {
        bool nxt = (c0 + 32 < KQ);
        uint4 pa0,pa1,pb0,pb1;
        if (nxt) {
            pa0 = load_cat8(node_embed, m0 + a_row,      c0+32 + a_seg*8);
            pa1 = load_cat8(node_embed, m0 + a_row + 64, c0+32 + a_seg*8);
            pb0 = *(const uint4*)(Wg + (size_t)(c0+32+b_row   )*D_ + j0 + b_seg*8);
            pb1 = *(const uint4*)(Wg + (size_t)(c0+32+b_row+16)*D_ + j0 + b_seg*8);
        }
        #pragma unroll
        for (int ks = 0; ks < 2; ks++) {
            unsigned a0,a1,a2,a3;
            unsigned bfr[4][2];
            #pragma unroll
            for (int nt=0; nt<4; nt++) {
                unsigned addr = b_base + (unsigned)((ks*16*136 + nt*8) * 2);
                LDSM_X2T(bfr[nt][0], bfr[nt][1], addr);
            }
            #pragma unroll
            for (int mt=0; mt<4; mt++) {
                unsigned addr = a_base + (unsigned)((mt*16*40 + ks*16) * 2);
                LDSM_X4(a0,a1,a2,a3, addr);
                #pragma unroll
                for (int nt=0; nt<4; nt++)
                    MMA16816(acc[mt][nt], a0,a1,a2,a3, bfr[nt][0], bfr[nt][1]);
            }
        }
        __syncthreads();
        if (nxt) {
            *(uint4*)&As[(a_row   )*40 + a_seg*8] = pa0;
            *(uint4*)&As[(a_row+64)*40 + a_seg*8] = pa1;
            *(uint4*)&Bs[(b_row   )*136 + b_seg*8] = pb0;
            *(uint4*)&Bs[(b_row+16)*136 + b_seg*8] = pb1;
            __syncthreads();
        }
    }

    #pragma unroll
    for (int mt=0; mt<4; mt++) {
        #pragma unroll
        for (int half=0; half<2; half++) {
            int i = m0 + warp_m*64 + mt*16 + quad + half*8;
            int bb = i >> 11, ntok = i & (N_-1);
            #pragma unroll
            for (int nt=0; nt<4; nt++) {
                int jj = j0 + warp_n*32 + nt*8 + qlane*2;
                float2 bv = *(const float2*)(bias + jj);
                float v0 = acc[mt][nt][half*2+0] + bv.x;
                float v1 = acc[mt][nt][half*2+1] + bv.y;
                bf16* dst;
                if (chunk == 0)      dst = g_q16 + (size_t)i*D_ + jj;
                else if (chunk <= 2) dst = g_k16 + ((size_t)(bb*R_ + (chunk-1))*N_ + ntok)*D_ + jj;
                else                 dst = g_v16 + ((size_t)(bb*R_ + (chunk-3))*N_ + ntok)*D_ + jj;
                *(bf162*)dst = __float22bfloat162_rn(make_float2(v0, v1));
            }
        }
    }
}

// ============ fused attention (R7-proven shape: 512 threads, 16 warps) ============
// S phase:  wm = warp&7 (16 q-rows), wd = warp>>3 (kv-half of 32)
// PV phase: wp_m = warp&3 (32 q-rows), wp_d = warp>>2 (d-quarter of 64)
// smem: q[128][264] | K 2x[64][264] | V 2x[64][264] | P[128][72] | rs[2][128]
#define SM_Q   0
#define SM_K   67584
#define SM_V   135168
#define SM_P   202752
#define SM_RS  221184
#define SM_TOT 222208
#define NTILE  (N_/64)

__global__ void __launch_bounds__(512, 1) k_attn(const int* __restrict__ adj) {
    extern __shared__ char dsm[];
    unsigned sbase = smem_u32(dsm);
    int tid = threadIdx.x;
    int l = tid & 31, warp = tid >> 5;
    int wm = warp & 7, wd = warp >> 3;
    int wp_m = warp & 3, wp_d = warp >> 2;
    int quad = l >> 2, qlane = l & 3;

    int m0 = blockIdx.x * 128;
    int p  = blockIdx.y;

    const bf16* gq = g_q16 + ((size_t)(p >> 1)*N_ + m0)*D_;
    const bf16* gk = g_k16 + (size_t)p*N_*D_;
    const bf16* gv = g_v16 + (size_t)p*N_*D_;
    // adj rows for this warp's two 8-row groups, int2 granularity.
    // Base folds in wd*32 cols + qlane; per tile t stride = 64 ints = 32 int2.
    const int2* adj0 = (const int2*)(adj + ((size_t)p*N_ + m0 + wm*16 + quad    )*N_ + wd*32) + qlane;
    const int2* adj8 = (const int2*)(adj + ((size_t)p*N_ + m0 + wm*16 + quad + 8)*N_ + wd*32) + qlane;

    // ---- preload q (128x256) + tile 0 K,V ----
    {
        #pragma unroll
        for (int it = 0; it < 8; it++) {
            int c = it*512 + tid;
            int row = c >> 5, seg = c & 31;
            CPA16(sbase + SM_Q + (unsigned)(row*528 + seg*16),
                  gq + (size_t)row*D_ + seg*8);
        }
        #pragma unroll
        for (int it = 0; it < 4; it++) {
            int c = it*512 + tid;
            int row = c >> 5, seg = c & 31;
            CPA16(sbase + SM_K + (unsigned)(row*528 + seg*16),
                  gk + (size_t)row*D_ + seg*8);
            CPA16(sbase + SM_V + (unsigned)(row*528 + seg*16),
                  gv + (size_t)row*D_ + seg*8);
        }
        CPA_COMMIT();
    }

    float o[2][8][4];
    #pragma unroll
    for (int m=0;m<2;m++)
        #pragma unroll
        for (int i=0;i<8;i++)
            { o[m][i][0]=0.f;o[m][i][1]=0.f;o[m][i][2]=0.f;o[m][i][3]=0.f; }
    float rs0 = 0.f, rs1 = 0.f;

    unsigned qa = sbase + SM_Q +
        (unsigned)(((wm*16 + (l & 7) + ((l >> 3) & 1)*8)*264 + (l >> 4)*8) * 2);
    unsigned kb = (unsigned)(((wd*32 + (l & 7) + ((l >> 4) & 1)*8)*264 + ((l >> 3) & 1)*8) * 2);
    unsigned pa = sbase + SM_P +
        (unsigned)(((wp_m*32 + (l & 7) + ((l >> 3) & 1)*8)*72 + (l >> 4)*8) * 2);
    unsigned vb = (unsigned)(((l & 15)*264 + wp_d*64 + ((l >> 4) & 1)*8) * 2);

    bf16* Psm = (bf16*)(dsm + SM_P);
    float* rsm = (float*)(dsm + SM_RS);

    for (int t = 0; t < NTILE; t++) {
        int buf = t & 1;
        CPA_WAIT0();
        __syncthreads();
        if (t + 1 < NTILE) {
            const bf16* gk1 = gk + (size_t)(t+1)*64*D_;
            const bf16* gv1 = gv + (size_t)(t+1)*64*D_;
            unsigned kd = sbase + SM_K + (unsigned)((buf^1))*33792u;
            unsigned vd = sbase + SM_V + (unsigned)((buf^1))*33792u;
            #pragma unroll
            for (int it = 0; it < 4; it++) {
                int c = it*512 + tid;
                int row = c >> 5, seg = c & 31;
                CPA16(kd + (unsigned)(row*528 + seg*16), gk1 + (size_t)row*D_ + seg*8);
                CPA16(vd + (unsigned)(row*528 + seg*16), gv1 + (size_t)row*D_ + seg*8);
            }
            CPA_COMMIT();
        }

        // ---- prefetch adj words for this tile (consumed after S MMAs) ----
        int2 am[8];
        #pragma unroll
        for (int nt = 0; nt < 4; nt++) {
            am[nt]     = adj0[t*32 + nt*4];
            am[4 + nt] = adj8[t*32 + nt*4];
        }

        // ---- S = q @ K^T for this warp's m16 x kv32 slice ----
        unsigned kbb = sbase + SM_K + (unsigned)buf*33792u + kb;
        float sc[4][4];
        #pragma unroll
        for (int i=0;i<4;i++){sc[i][0]=0.f;sc[i][1]=0.f;sc[i][2]=0.f;sc[i][3]=0.f;}
        #pragma unroll
        for (int ks = 0; ks < 16; ks++) {
            unsigned a0,a1,a2,a3;
            LDSM_X4(a0,a1,a2,a3, qa + (unsigned)(ks*32));
            #pragma unroll
            for (int nt16 = 0; nt16 < 2; nt16++) {
                unsigned b0,b1,b2,b3;
                LDSM_X4(b0,b1,b2,b3, kbb + (unsigned)((nt16*16*264 + ks*16) * 2));
                MMA16816(sc[nt16*2  ], a0,a1,a2,a3, b0,b1);
                MMA16816(sc[nt16*2+1], a0,a1,a2,a3, b2,b3);
            }
        }

        // ---- mask + exp + rowsum + P to smem ----
        {
            int r0 = wm*16 + quad;
            #pragma unroll
            for (int nt = 0; nt < 4; nt++) {
                float e00 = am[nt].x     ? __expf(sc[nt][0]*0.0625f) : 0.f;
                float e01 = am[nt].y     ? __expf(sc[nt][1]*0.0625f) : 0.f;
                float e10 = am[4+nt].x   ? __expf(sc[nt][2]*0.0625f) : 0.f;
                float e11 = am[4+nt].y   ? __expf(sc[nt][3]*0.0625f) : 0.f;
                rs0 += e00 + e01;
                rs1 += e10 + e11;
                int col = wd*32 + nt*8 + qlane*2;
                *(unsigned*)(Psm + r0*72 + col)     = pk2(e00, e01);
                *(unsigned*)(Psm + (r0+8)*72 + col) = pk2(e10, e11);
            }
        }
        __syncthreads();

        // ---- O += P @ V : warp slice m32 x d64, k = kv64 ----
        unsigned vbb = sbase + SM_V + (unsigned)buf*33792u + vb;
        #pragma unroll
        for (int ks2 = 0; ks2 < 4; ks2++) {
            unsigned b[4][4];
            #pragma unroll
            for (int nt16 = 0; nt16 < 4; nt16++)
                LDSM_X4T(b[nt16][0],b[nt16][1],b[nt16][2],b[nt16][3],
                         vbb + (unsigned)((ks2*16*264 + nt16*16) * 2));
            #pragma unroll
            for (int mt = 0; mt < 2; mt++) {
                unsigned a0,a1,a2,a3;
                LDSM_X4(a0,a1,a2,a3, pa + (unsigned)((mt*16*72 + ks2*16) * 2));
                #pragma unroll
                for (int nt16 = 0; nt16 < 4; nt16++) {
                    MMA16816(o[mt][nt16*2  ], a0,a1,a2,a3, b[nt16][0], b[nt16][1]);
                    MMA16816(o[mt][nt16*2+1], a0,a1,a2,a3, b[nt16][2], b[nt16][3]);
                }
            }
        }
    }

    // ---- rowsum reduce (S-phase indexing) ----
    rs0 += __shfl_xor_sync(0xffffffffu, rs0, 1);
    rs0 += __shfl_xor_sync(0xffffffffu, rs0, 2);
    rs1 += __shfl_xor_sync(0xffffffffu, rs1, 1);
    rs1 += __shfl_xor_sync(0xffffffffu, rs1, 2);
    if (qlane == 0) {
        rsm[wd*128 + wm*16 + quad]     = rs0;
        rsm[wd*128 + wm*16 + quad + 8] = rs1;
    }
    __syncthreads();

    // ---- normalize + write (PV indexing: rows wp_m*32.., cols wp_d*64..) ----
    #pragma unroll
    for (int mt = 0; mt < 2; mt++) {
        int r = wp_m*32 + mt*16 + quad;
        float ta = rsm[r]     + rsm[128 + r];
        float tb = rsm[r + 8] + rsm[128 + r + 8];
        float ia = ta > 0.f ? __fdividef(1.f, ta) : 0.f;
        float ib = tb > 0.f ? __fdividef(1.f, tb) : 0.f;
        bf16* d0 = g_h16 + ((size_t)((p >> 1)*N_ + m0 + r))*(R_*D_) + (p & 1)*D_ + wp_d*64;
        bf16* d1 = d0 + (size_t)8*(R_*D_);
        #pragma unroll
        for (int nt = 0; nt < 8; nt++) {
            int col = nt*8 + qlane*2;
            *(unsigned*)(d0 + col) = pk2(o[mt][nt][0]*ia, o[mt][nt][1]*ia);
            *(unsigned*)(d1 + col) = pk2(o[mt][nt][2]*ib, o[mt][nt][3]*ib);
        }
    }
}

// ============ h_fused GEMM + relu + residual + LN (mma.sync, proven) ============
__global__ void __launch_bounds__(256) k_fused16(
        const float* __restrict__ node_embed,
        const float* __restrict__ WF_b,
        const float* __restrict__ ln_g, const float* __restrict__ ln_b,
        float* __restrict__ out) {
    __shared__ bf16 As[64*40];
    __shared__ bf16 Bs[32*264];
    __shared__ float2 part[64][4];
    int tid = threadIdx.x;
    int l = tid & 31, warp = tid >> 5;
    int warp_m = warp & 1, warp_n = warp >> 1;
    int quad = l >> 2, qlane = l & 3;
    int m0 = blockIdx.x * 64;

    float acc[2][8][4];
    #pragma unroll
    for (int i=0;i<2;i++) for (int j=0;j<8;j++) for (int c=0;c<4;c++) acc[i][j][c]=0.f;

    int a_row = tid >> 2, a_seg = tid & 3;
    int b_row = tid >> 5, b_seg = tid & 31;

    int arow = (l & 7) + ((l >> 3) & 1) * 8;
    int acol = (l >> 4) * 8;
    unsigned a_base = smem_u32(As) + (unsigned)(((warp_m*32 + arow)*40 + acol) * 2);
    int lt = l & 15;
    unsigned b_base = smem_u32(Bs) + (unsigned)((lt*264 + warp_n*64) * 2);

    {
        *(uint4*)&As[a_row*40 + a_seg*8] =
            *(const uint4*)(g_h16 + (size_t)(m0+a_row)*(R_*D_) + a_seg*8);
        #pragma unroll
        for (int it=0; it<4; it++) {
            int rb = b_row + it*8;
            *(uint4*)&Bs[rb*264 + b_seg*8] =
                *(const uint4*)(g_wf16 + (size_t)rb*D_ + b_seg*8);
        }
    }
    __syncthreads();

    for (int c0 = 0; c0 < R_*D_; c0 += 32) {
        bool nxt = (c0 + 32 < R_*D_);
        uint4 pa0, pb[4];
        if (nxt) {
            pa0 = *(const uint4*)(g_h16 + (size_t)(m0+a_row)*(R_*D_) + c0+32 + a_seg*8);
            #pragma unroll
            for (int it=0; it<4; it++)
                pb[it] = *(const uint4*)(g_wf16 + (size_t)(c0+32+b_row+it*8)*D_ + b_seg*8);
        }
        #pragma unroll
        for (int ks = 0; ks < 2; ks++) {
            unsigned a0,a1,a2,a3;
            unsigned bfr[8][2];
            #pragma unroll
            for (int nt=0; nt<8; nt++) {
                unsigned addr = b_base + (unsigned)((ks*16*264 + nt*8) * 2);
                LDSM_X2T(bfr[nt][0], bfr[nt][1], addr);
            }
            #pragma unroll
            for (int mt=0; mt<2; mt++) {
                unsigned addr = a_base + (unsigned)((mt*16*40 + ks*16) * 2);
                LDSM_X4(a0,a1,a2,a3, addr);
                #pragma unroll
                for (int nt=0; nt<8; nt++)
                    MMA16816(acc[mt][nt], a0,a1,a2,a3, bfr[nt][0], bfr[nt][1]);
            }
        }
        __syncthreads();
        if (nxt) {
            *(uint4*)&As[a_row*40 + a_seg*8] = pa0;
            #pragma unroll
            for (int it=0; it<4; it++)
                *(uint4*)&Bs[(b_row+it*8)*264 + b_seg*8] = pb[it];
            __syncthreads();
        }
    }

    #pragma unroll
    for (int mt=0; mt<2; mt++) {
        #pragma unroll
        for (int half=0; half<2; half++) {
            int row_l = warp_m*32 + mt*16 + quad + half*8;
            int grow = m0 + row_l;
            float s = 0.f, sq = 0.f;
            #pragma unroll
            for (int nt=0; nt<8; nt++) {
                int col = warp_n*64 + nt*8 + qlane*2;
                float2 bb = *(const float2*)(WF_b + col);
                float h0 = acc[mt][nt][half*2+0] + bb.x; h0 = h0 > 0.f ? h0 : 0.f;
                float h1 = acc[mt][nt][half*2+1] + bb.y; h1 = h1 > 0.f ? h1 : 0.f;
                float2 ne = *(const float2*)(node_embed + (size_t)grow*D_ + col);
                float y0 = ne.x + h0, y1 = ne.y + h1;
                acc[mt][nt][half*2+0] = y0;
                acc[mt][nt][half*2+1] = y1;
                s += y0 + y1;
                sq = fmaf(y0, y0, fmaf(y1, y1, sq));
            }
            s  += __shfl_xor_sync(0xffffffffu, s, 1);
            s  += __shfl_xor_sync(0xffffffffu, s, 2);
            sq += __shfl_xor_sync(0xffffffffu, sq, 1);
            sq += __shfl_xor_sync(0xffffffffu, sq, 2);
            if (qlane == 0) part[row_l][warp_n] = make_float2(s, sq);
        }
    }
    __syncthreads();
    #pragma unroll
    for (int mt=0; mt<2; mt++) {
        #pragma unroll
        for (int half=0; half<2; half++) {
            int row_l = warp_m*32 + mt*16 + quad + half*8;
            int grow = m0 + row_l;
            float s = 0.f, sq = 0.f;
            #pragma unroll
            for (int w=0; w<4; w++) { float2 pp = part[row_l][w]; s += pp.x; sq += pp.y; }
            float mu = s * (1.0f/256.0f);
            float var = sq * (1.0f/256.0f) - mu*mu;
            float rstd = rsqrtf(var + 1e-5f);
            #pragma unroll
            for (int nt=0; nt<8; nt++) {
                int col = warp_n*64 + nt*8 + qlane*2;
                float2 gg = *(const float2*)(ln_g + col);
                float2 bb = *(const float2*)(ln_b + col);
                float y0 = acc[mt][nt][half*2+0];
                float y1 = acc[mt][nt][half*2+1];
                float2 o;
                o.x = (y0 - mu) * rstd * gg.x + bb.x;
                o.y = (y1 - mu) * rstd * gg.y + bb.y;
                *(float2*)(out + (size_t)grow*D_ + col) = o;
            }
        }
    }
}

// ---------------- launch ----------------
extern "C" void kernel_launch(void* const* d_in, const int* in_sizes, int n_in,
                              void* d_out, int out_size) {
    const float* node_embed = (const float*)d_in[0];
    const float* input_x    = (const float*)d_in[1];
    const int*   adj        = (const int*)  d_in[2];
    const float* WQi_w      = (const float*)d_in[3];
    const float* WQi_b      = (const float*)d_in[4];
    const float* WQ_w       = (const float*)d_in[5];
    const float* WQ_b       = (const float*)d_in[6];
    const float* WK_w       = (const float*)d_in[7];
    const float* WK_b       = (const float*)d_in[8];
    const float* WV_w       = (const float*)d_in[9];
    const float* WV_b       = (const float*)d_in[10];
    const float* WF_w       = (const float*)d_in[11];
    const float* WF_b       = (const float*)d_in[12];
    const float* ln_g       = (const float*)d_in[13];
    const float* ln_b       = (const float*)d_in[14];
    float* out = (float*)d_out;

    cudaFuncSetAttribute(k_attn, cudaFuncAttributeMaxDynamicSharedMemorySize, SM_TOT);

    k_x1      <<<B_, F_>>>(input_x, WQi_w, WQi_b);
    k_cvtw    <<<1216, 256>>>(WQ_w, WK_w, WV_w, WF_w);
    k_qkv16   <<<dim3(10, 128), 256>>>(node_embed, WQ_b, WK_b, WV_b);
    k_attn    <<<dim3(16, B_*R_), 512, SM_TOT>>>(adj);
    k_fused16 <<<M_TOT/64, 256>>>(node_embed, WF_b, ln_g, ln_b, out);
}

// round 11
// speedup vs baseline: 1.6148x; 1.0096x over previous
#include <cuda_runtime.h>
#include <cuda_bf16.h>
#include <math.h>

#define B_ 8
#define N_ 2048
#define D_ 256
#define F_ 128
#define R_ 2
#define KQ 384            // D_+F_
#define M_TOT (B_*N_)     // 16384

typedef __nv_bfloat16 bf16;
typedef __nv_bfloat162 bf162;

// ---------------- scratch ----------------
__device__ float g_x1[B_*F_];
__device__ bf16  g_q16[(size_t)M_TOT*D_];
__device__ bf16  g_k16[(size_t)B_*R_*N_*D_];
__device__ bf16  g_v16[(size_t)B_*R_*N_*D_];
__device__ bf16  g_h16[(size_t)M_TOT*R_*D_];
__device__ bf16  g_wq16[KQ*D_];
__device__ bf16  g_wk16[R_*KQ*D_];
__device__ bf16  g_wv16[R_*KQ*D_];
__device__ bf16  g_wf16[R_*D_*D_];

// ---------------- PTX helpers ----------------
__device__ __forceinline__ unsigned smem_u32(const void* p) {
    return (unsigned)__cvta_generic_to_shared(p);
}
#define LDSM_X4(r0,r1,r2,r3,addr) \
    asm volatile("ldmatrix.sync.aligned.m8n8.x4.shared.b16 {%0,%1,%2,%3}, [%4];" \
        : "=r"(r0),"=r"(r1),"=r"(r2),"=r"(r3) : "r"(addr))
#define LDSM_X4T(r0,r1,r2,r3,addr) \
    asm volatile("ldmatrix.sync.aligned.m8n8.x4.trans.shared.b16 {%0,%1,%2,%3}, [%4];" \
        : "=r"(r0),"=r"(r1),"=r"(r2),"=r"(r3) : "r"(addr))
#define LDSM_X2T(r0,r1,addr) \
    asm volatile("ldmatrix.sync.aligned.m8n8.x2.trans.shared.b16 {%0,%1}, [%2];" \
        : "=r"(r0),"=r"(r1) : "r"(addr))
#define MMA16816(c,a0,a1,a2,a3,b0,b1) \
    asm volatile("mma.sync.aligned.m16n8k16.row.col.f32.bf16.bf16.f32 " \
        "{%0,%1,%2,%3},{%4,%5,%6,%7},{%8,%9},{%0,%1,%2,%3};" \
        : "+f"(c[0]),"+f"(c[1]),"+f"(c[2]),"+f"(c[3]) \
        : "r"(a0),"r"(a1),"r"(a2),"r"(a3),"r"(b0),"r"(b1))
#define CPA16(s,g) asm volatile("cp.async.cg.shared.global [%0], [%1], 16;" :: "r"(s), "l"(g))
#define CPA_COMMIT() asm volatile("cp.async.commit_group;" ::: "memory")
#define CPA_WAIT1() asm volatile("cp.async.wait_group 1;" ::: "memory")

static __device__ __forceinline__ unsigned pk2(float a, float b) {
    bf162 t = __float22bfloat162_rn(make_float2(a, b));
    return *(unsigned*)&t;
}

// ---------------- x1 ----------------
__global__ void k_x1(const float* __restrict__ input_x,
                     const float* __restrict__ Ww,
                     const float* __restrict__ Wb) {
    __shared__ float row[F_];
    int b = blockIdx.x, j = threadIdx.x;
    row[j] = input_x[b*F_ + j];
    __syncthreads();
    float s = Wb[j];
    #pragma unroll 4
    for (int c = 0; c < F_; c++) s = fmaf(row[c], Ww[c*F_ + j], s);
    g_x1[b*F_ + j] = s;
}

// ---------------- weights to bf16 ----------------
__global__ void k_cvtw(const float* __restrict__ wq, const float* __restrict__ wk,
                       const float* __restrict__ wv, const float* __restrict__ wf) {
    int i = blockIdx.x * blockDim.x + threadIdx.x;
    int e = i * 2;
    const int SQ = KQ*D_, SK = R_*KQ*D_, SF = R_*D_*D_;
    if (e < SQ) {
        *(bf162*)(g_wq16 + e) = __float22bfloat162_rn(*(const float2*)(wq + e));
    } else if (e < SQ + SK) {
        int o = e - SQ;
        *(bf162*)(g_wk16 + o) = __float22bfloat162_rn(*(const float2*)(wk + o));
    } else if (e < SQ + 2*SK) {
        int o = e - SQ - SK;
        *(bf162*)(g_wv16 + o) = __float22bfloat162_rn(*(const float2*)(wv + o));
    } else if (e < SQ + 2*SK + SF) {
        int o = e - SQ - 2*SK;
        *(bf162*)(g_wf16 + o) = __float22bfloat162_rn(*(const float2*)(wf + o));
    }
}

// inline concat loader: 8 bf16 of [node_embed | x1] row m, cols c..c+7
__device__ __forceinline__ uint4 load_cat8(const float* __restrict__ ne, int m, int c) {
    float4 f0, f1;
    if (c < D_) {
        const float* p = ne + (size_t)m*D_ + c;
        f0 = *(const float4*)p; f1 = *(const float4*)(p + 4);
    } else {
        const float* p = g_x1 + (size_t)(m >> 11)*F_ + (c - D_);
        f0 = *(const float4*)p; f1 = *(const float4*)(p + 4);
    }
    uint4 r;
    r.x = pk2(f0.x, f0.y); r.y = pk2(f0.z, f0.w);
    r.z = pk2(f1.x, f1.y); r.w = pk2(f1.z, f1.w);
    return r;
}

// ============ qkv GEMM (proven shape: CTA 128x128, 8 warps 64x32) ============
__global__ void __launch_bounds__(256) k_qkv16(
        const float* __restrict__ node_embed,
        const float* __restrict__ WQ_b, const float* __restrict__ WK_b,
        const float* __restrict__ WV_b) {
    __shared__ bf16 As[128*40];
    __shared__ bf16 Bs[32*136];
    int tid = threadIdx.x;
    int l = tid & 31, warp = tid >> 5;
    int warp_m = warp & 1, warp_n = warp >> 1;
    int quad = l >> 2, qlane = l & 3;

    int bn = blockIdx.x;
    int m0 = blockIdx.y * 128;
    int chunk = bn >> 1;
    int j0 = (bn & 1) * 128;

    const bf16* Wg; const float* bias;
    if (chunk == 0)      { Wg = g_wq16;                           bias = WQ_b; }
    else if (chunk <= 2) { Wg = g_wk16 + (size_t)(chunk-1)*KQ*D_; bias = WK_b + (chunk-1)*D_; }
    else                 { Wg = g_wv16 + (size_t)(chunk-3)*KQ*D_; bias = WV_b + (chunk-3)*D_; }

    float acc[4][4][4];
    #pragma unroll
    for (int i=0;i<4;i++) for (int j=0;j<4;j++) for (int c=0;c<4;c++) acc[i][j][c]=0.f;

    int a_row = tid >> 2, a_seg = tid & 3;
    int b_row = tid >> 4, b_seg = tid & 15;

    int arow = (l & 7) + ((l >> 3) & 1) * 8;
    int acol = (l >> 4) * 8;
    unsigned a_base = smem_u32(As) + (unsigned)(((warp_m*64 + arow)*40 + acol) * 2);
    int lt = l & 15;
    unsigned b_base = smem_u32(Bs) + (unsigned)((lt*136 + warp_n*32) * 2);

    {
        #pragma unroll
        for (int it=0; it<2; it++) {
            int r = a_row + it*64;
            *(uint4*)&As[r*40 + a_seg*8] = load_cat8(node_embed, m0 + r, a_seg*8);
            int rb = b_row + it*16;
            *(uint4*)&Bs[rb*136 + b_seg*8] =
                *(const uint4*)(Wg + (size_t)rb*D_ + j0 + b_seg*8);
        }
    }
    __syncthreads();

    for (int c0 = 0; c0 < KQ; c0 += 32) {
        bool nxt = (c0 + 32 < KQ);
        uint4 pa0,pa1,pb0,pb1;
        if (nxt) {
            pa0 = load_cat8(node_embed, m0 + a_row,      c0+32 + a_seg*8);
            pa1 = load_cat8(node_embed, m0 + a_row + 64, c0+32 + a_seg*8);
            pb0 = *(const uint4*)(Wg + (size_t)(c0+32+b_row   )*D_ + j0 + b_seg*8);
            pb1 = *(const uint4*)(Wg + (size_t)(c0+32+b_row+16)*D_ + j0 + b_seg*8);
        }
        #pragma unroll
        for (int ks = 0; ks < 2; ks++) {
            unsigned a0,a1,a2,a3;
            unsigned bfr[4][2];
            #pragma unroll
            for (int nt=0; nt<4; nt++) {
                unsigned addr = b_base + (unsigned)((ks*16*136 + nt*8) * 2);
                LDSM_X2T(bfr[nt][0], bfr[nt][1], addr);
            }
            #pragma unroll
            for (int mt=0; mt<4; mt++) {
                unsigned addr = a_base + (unsigned)((mt*16*40 + ks*16) * 2);
                LDSM_X4(a0,a1,a2,a3, addr);
                #pragma unroll
                for (int nt=0; nt<4; nt++)
                    MMA16816(acc[mt][nt], a0,a1,a2,a3, bfr[nt][0], bfr[nt][1]);
            }
        }
        __syncthreads();
        if (nxt) {
            *(uint4*)&As[(a_row   )*40 + a_seg*8] = pa0;
            *(uint4*)&As[(a_row+64)*40 + a_seg*8] = pa1;
            *(uint4*)&Bs[(b_row   )*136 + b_seg*8] = pb0;
            *(uint4*)&Bs[(b_row+16)*136 + b_seg*8] = pb1;
            __syncthreads();
        }
    }

    #pragma unroll
    for (int mt=0; mt<4; mt++) {
        #pragma unroll
        for (int half=0; half<2; half++) {
            int i = m0 + warp_m*64 + mt*16 + quad + half*8;
            int bb = i >> 11, ntok = i & (N_-1);
            #pragma unroll
            for (int nt=0; nt<4; nt++) {
                int jj = j0 + warp_n*32 + nt*8 + qlane*2;
                float2 bv = *(const float2*)(bias + jj);
                float v0 = acc[mt][nt][half*2+0] + bv.x;
                float v1 = acc[mt][nt][half*2+1] + bv.y;
                bf16* dst;
                if (chunk == 0)      dst = g_q16 + (size_t)i*D_ + jj;
                else if (chunk <= 2) dst = g_k16 + ((size_t)(bb*R_ + (chunk-1))*N_ + ntok)*D_ + jj;
                else                 dst = g_v16 + ((size_t)(bb*R_ + (chunk-3))*N_ + ntok)*D_ + jj;
                *(bf162*)dst = __float22bfloat162_rn(make_float2(v0, v1));
            }
        }
    }
}

// ============ fused attention: 64 q-rows/CTA, 256 thr, 2 CTAs/SM ============
// 8 warps: wm = warp&3 (16 q-rows), wd = warp>>2.
// S phase:  warp tile m16 x kv32 (wd = kv-half of 32), k=256
// PV phase: warp tile m16 x d128 (wd = d-half of 128), k=64
// smem: q[64][264] | K[64][264] | V[64][264] | P[64][72] | rs[2][64]
// cp.async rotating schedule: K(t+1) issued post-S barrier (overlaps PV(t)),
// V(t+1) issued post-PV barrier (overlaps S(t+1)); invariant at each wait_group 1:
// pending = {older: needed now, newer: next phase}.
#define AT_Q   0
#define AT_K   33792
#define AT_V   67584
#define AT_P   101376
#define AT_RS  110592
#define AT_TOT 111104
#define NT64   (N_/64)

__global__ void __launch_bounds__(256, 2) k_attn(const int* __restrict__ adj) {
    extern __shared__ char dsm[];
    unsigned sbase = smem_u32(dsm);
    int tid = threadIdx.x;
    int l = tid & 31, warp = tid >> 5;   // 8 warps
    int wm = warp & 3, wd = warp >> 2;
    int quad = l >> 2, qlane = l & 3;

    int m0 = blockIdx.x * 64;
    int p  = blockIdx.y;

    const bf16* gq = g_q16 + ((size_t)(p >> 1)*N_ + m0)*D_;
    const bf16* gk = g_k16 + (size_t)p*N_*D_;
    const bf16* gv = g_v16 + (size_t)p*N_*D_;
    // adj rows for this warp's two 8-row groups; per-tile stride = 64 ints = 32 int2
    const int2* adj0 = (const int2*)(adj + ((size_t)p*N_ + m0 + wm*16 + quad    )*N_ + wd*32) + qlane;
    const int2* adj8 = (const int2*)(adj + ((size_t)p*N_ + m0 + wm*16 + quad + 8)*N_ + wd*32) + qlane;

    // ---- preload: group0 = q + K(0), group1 = V(0) ----
    #pragma unroll
    for (int it = 0; it < 8; it++) {
        int c = it*256 + tid;
        int row = c >> 5, seg = c & 31;
        CPA16(sbase + AT_Q + (unsigned)(row*528 + seg*16), gq + (size_t)row*D_ + seg*8);
    }
    #pragma unroll
    for (int it = 0; it < 8; it++) {
        int c = it*256 + tid;
        int row = c >> 5, seg = c & 31;
        CPA16(sbase + AT_K + (unsigned)(row*528 + seg*16), gk + (size_t)row*D_ + seg*8);
    }
    CPA_COMMIT();
    #pragma unroll
    for (int it = 0; it < 8; it++) {
        int c = it*256 + tid;
        int row = c >> 5, seg = c & 31;
        CPA16(sbase + AT_V + (unsigned)(row*528 + seg*16), gv + (size_t)row*D_ + seg*8);
    }
    CPA_COMMIT();

    float o[16][4];
    #pragma unroll
    for (int i=0;i<16;i++) { o[i][0]=0.f;o[i][1]=0.f;o[i][2]=0.f;o[i][3]=0.f; }
    float rs0 = 0.f, rs1 = 0.f;

    unsigned qa = sbase + AT_Q +
        (unsigned)(((wm*16 + (l & 7) + ((l >> 3) & 1)*8)*264 + (l >> 4)*8) * 2);
    unsigned kbb = sbase + AT_K +
        (unsigned)(((wd*32 + (l & 7) + ((l >> 4) & 1)*8)*264 + ((l >> 3) & 1)*8) * 2);
    unsigned pa = sbase + AT_P +
        (unsigned)(((wm*16 + (l & 7) + ((l >> 3) & 1)*8)*72 + (l >> 4)*8) * 2);
    unsigned vbb = sbase + AT_V +
        (unsigned)(((l & 15)*264 + wd*128 + ((l >> 4) & 1)*8) * 2);

    bf16* Psm = (bf16*)(dsm + AT_P);
    float* rsm = (float*)(dsm + AT_RS);

    for (int t = 0; t < NT64; t++) {
        // wait K(t): pending {K(t) older, V(t) newer} -> wait_group 1
        CPA_WAIT1();
        __syncthreads();

        // adj prefetch (consumed after S MMAs)
        int2 am[8];
        #pragma unroll
        for (int nt = 0; nt < 4; nt++) {
            am[nt]     = adj0[t*32 + nt*4];
            am[4 + nt] = adj8[t*32 + nt*4];
        }

        // ---- S = q @ K^T : warp m16 x kv32, k=256 ----
        float sc[4][4];
        #pragma unroll
        for (int i=0;i<4;i++){sc[i][0]=0.f;sc[i][1]=0.f;sc[i][2]=0.f;sc[i][3]=0.f;}
        #pragma unroll
        for (int ks = 0; ks < 16; ks++) {
            unsigned a0,a1,a2,a3;
            LDSM_X4(a0,a1,a2,a3, qa + (unsigned)(ks*32));
            #pragma unroll
            for (int nt16 = 0; nt16 < 2; nt16++) {
                unsigned b0,b1,b2,b3;
                LDSM_X4(b0,b1,b2,b3, kbb + (unsigned)((nt16*16*264 + ks*16) * 2));
                MMA16816(sc[nt16*2  ], a0,a1,a2,a3, b0,b1);
                MMA16816(sc[nt16*2+1], a0,a1,a2,a3, b2,b3);
            }
        }

        // ---- mask + exp + rowsum + P to smem ----
        {
            int r0 = wm*16 + quad;
            #pragma unroll
            for (int nt = 0; nt < 4; nt++) {
                float e00 = am[nt].x   ? __expf(sc[nt][0]*0.0625f) : 0.f;
                float e01 = am[nt].y   ? __expf(sc[nt][1]*0.0625f) : 0.f;
                float e10 = am[4+nt].x ? __expf(sc[nt][2]*0.0625f) : 0.f;
                float e11 = am[4+nt].y ? __expf(sc[nt][3]*0.0625f) : 0.f;
                rs0 += e00 + e01;
                rs1 += e10 + e11;
                int col = wd*32 + nt*8 + qlane*2;
                *(unsigned*)(Psm + r0*72 + col)     = pk2(e00, e01);
                *(unsigned*)(Psm + (r0+8)*72 + col) = pk2(e10, e11);
            }
        }
        __syncthreads();   // P ready; K buffer free

        // issue K(t+1) (overlaps PV(t))
        if (t + 1 < NT64) {
            const bf16* gk1 = gk + (size_t)(t+1)*64*D_;
            #pragma unroll
            for (int it = 0; it < 8; it++) {
                int c = it*256 + tid;
                int row = c >> 5, seg = c & 31;
                CPA16(sbase + AT_K + (unsigned)(row*528 + seg*16),
                      gk1 + (size_t)row*D_ + seg*8);
            }
        }
        CPA_COMMIT();

        // wait V(t): pending {V(t) older, K(t+1) newer} -> wait_group 1
        CPA_WAIT1();
        __syncthreads();

        // ---- O += P @ V : warp m16 x d128, k=64 ----
        #pragma unroll
        for (int ks2 = 0; ks2 < 4; ks2++) {
            unsigned a0,a1,a2,a3;
            LDSM_X4(a0,a1,a2,a3, pa + (unsigned)(ks2*32));
            #pragma unroll
            for (int nt16 = 0; nt16 < 8; nt16++) {
                unsigned b0,b1,b2,b3;
                LDSM_X4T(b0,b1,b2,b3, vbb + (unsigned)((ks2*16*264 + nt16*16) * 2));
                MMA16816(o[nt16*2  ], a0,a1,a2,a3, b0,b1);
                MMA16816(o[nt16*2+1], a0,a1,a2,a3, b2,b3);
            }
        }
        __syncthreads();   // V buffer free

        // issue V(t+1) (overlaps S(t+1))
        if (t + 1 < NT64) {
            const bf16* gv1 = gv + (size_t)(t+1)*64*D_;
            #pragma unroll
            for (int it = 0; it < 8; it++) {
                int c = it*256 + tid;
                int row = c >> 5, seg = c & 31;
                CPA16(sbase + AT_V + (unsigned)(row*528 + seg*16),
                      gv1 + (size_t)row*D_ + seg*8);
            }
        }
        CPA_COMMIT();
    }

    // ---- rowsum publish + reduce over kv halves ----
    rs0 += __shfl_xor_sync(0xffffffffu, rs0, 1);
    rs0 += __shfl_xor_sync(0xffffffffu, rs0, 2);
    rs1 += __shfl_xor_sync(0xffffffffu, rs1, 1);
    rs1 += __shfl_xor_sync(0xffffffffu, rs1, 2);
    if (qlane == 0) {
        rsm[wd*64 + wm*16 + quad]     = rs0;
        rsm[wd*64 + wm*16 + quad + 8] = rs1;
    }
    __syncthreads();

    // ---- normalize + write (rows wm*16.., cols wd*128..) ----
    {
        int r = wm*16 + quad;
        float ta = rsm[r]     + rsm[64 + r];
        float tb = rsm[r + 8] + rsm[64 + r + 8];
        float ia = ta > 0.f ? __fdividef(1.f, ta) : 0.f;
        float ib = tb > 0.f ? __fdividef(1.f, tb) : 0.f;
        bf16* d0 = g_h16 + ((size_t)((p >> 1)*N_ + m0 + r))*(R_*D_) + (p & 1)*D_ + wd*128;
        bf16* d1 = d0 + (size_t)8*(R_*D_);
        #pragma unroll
        for (int nt = 0; nt < 16; nt++) {
            int col = nt*8 + qlane*2;
            *(unsigned*)(d0 + col) = pk2(o[nt][0]*ia, o[nt][1]*ia);
            *(unsigned*)(d1 + col) = pk2(o[nt][2]*ib, o[nt][3]*ib);
        }
    }
}

// ============ h_fused GEMM + relu + residual + LN (mma.sync, proven) ============
__global__ void __launch_bounds__(256) k_fused16(
        const float* __restrict__ node_embed,
        const float* __restrict__ WF_b,
        const float* __restrict__ ln_g, const float* __restrict__ ln_b,
        float* __restrict__ out) {
    __shared__ bf16 As[64*40];
    __shared__ bf16 Bs[32*264];
    __shared__ float2 part[64][4];
    int tid = threadIdx.x;
    int l = tid & 31, warp = tid >> 5;
    int warp_m = warp & 1, warp_n = warp >> 1;
    int quad = l >> 2, qlane = l & 3;
    int m0 = blockIdx.x * 64;

    float acc[2][8][4];
    #pragma unroll
    for (int i=0;i<2;i++) for (int j=0;j<8;j++) for (int c=0;c<4;c++) acc[i][j][c]=0.f;

    int a_row = tid >> 2, a_seg = tid & 3;
    int b_row = tid >> 5, b_seg = tid & 31;

    int arow = (l & 7) + ((l >> 3) & 1) * 8;
    int acol = (l >> 4) * 8;
    unsigned a_base = smem_u32(As) + (unsigned)(((warp_m*32 + arow)*40 + acol) * 2);
    int lt = l & 15;
    unsigned b_base = smem_u32(Bs) + (unsigned)((lt*264 + warp_n*64) * 2);

    {
        *(uint4*)&As[a_row*40 + a_seg*8] =
            *(const uint4*)(g_h16 + (size_t)(m0+a_row)*(R_*D_) + a_seg*8);
        #pragma unroll
        for (int it=0; it<4; it++) {
            int rb = b_row + it*8;
            *(uint4*)&Bs[rb*264 + b_seg*8] =
                *(const uint4*)(g_wf16 + (size_t)rb*D_ + b_seg*8);
        }
    }
    __syncthreads();

    for (int c0 = 0; c0 < R_*D_; c0 += 32) {
        bool nxt = (c0 + 32 < R_*D_);
        uint4 pa0, pb[4];
        if (nxt) {
            pa0 = *(const uint4*)(g_h16 + (size_t)(m0+a_row)*(R_*D_) + c0+32 + a_seg*8);
            #pragma unroll
            for (int it=0; it<4; it++)
                pb[it] = *(const uint4*)(g_wf16 + (size_t)(c0+32+b_row+it*8)*D_ + b_seg*8);
        }
        #pragma unroll
        for (int ks = 0; ks < 2; ks++) {
            unsigned a0,a1,a2,a3;
            unsigned bfr[8][2];
            #pragma unroll
            for (int nt=0; nt<8; nt++) {
                unsigned addr = b_base + (unsigned)((ks*16*264 + nt*8) * 2);
                LDSM_X2T(bfr[nt][0], bfr[nt][1], addr);
            }
            #pragma unroll
            for (int mt=0; mt<2; mt++) {
                unsigned addr = a_base + (unsigned)((mt*16*40 + ks*16) * 2);
                LDSM_X4(a0,a1,a2,a3, addr);
                #pragma unroll
                for (int nt=0; nt<8; nt++)
                    MMA16816(acc[mt][nt], a0,a1,a2,a3, bfr[nt][0], bfr[nt][1]);
            }
        }
        __syncthreads();
        if (nxt) {
            *(uint4*)&As[a_row*40 + a_seg*8] = pa0;
            #pragma unroll
            for (int it=0; it<4; it++)
                *(uint4*)&Bs[(b_row+it*8)*264 + b_seg*8] = pb[it];
            __syncthreads();
        }
    }

    #pragma unroll
    for (int mt=0; mt<2; mt++) {
        #pragma unroll
        for (int half=0; half<2; half++) {
            int row_l = warp_m*32 + mt*16 + quad + half*8;
            int grow = m0 + row_l;
            float s = 0.f, sq = 0.f;
            #pragma unroll
            for (int nt=0; nt<8; nt++) {
                int col = warp_n*64 + nt*8 + qlane*2;
                float2 bb = *(const float2*)(WF_b + col);
                float h0 = acc[mt][nt][half*2+0] + bb.x; h0 = h0 > 0.f ? h0 : 0.f;
                float h1 = acc[mt][nt][half*2+1] + bb.y; h1 = h1 > 0.f ? h1 : 0.f;
                float2 ne = *(const float2*)(node_embed + (size_t)grow*D_ + col);
                float y0 = ne.x + h0, y1 = ne.y + h1;
                acc[mt][nt][half*2+0] = y0;
                acc[mt][nt][half*2+1] = y1;
                s += y0 + y1;
                sq = fmaf(y0, y0, fmaf(y1, y1, sq));
            }
            s  += __shfl_xor_sync(0xffffffffu, s, 1);
            s  += __shfl_xor_sync(0xffffffffu, s, 2);
            sq += __shfl_xor_sync(0xffffffffu, sq, 1);
            sq += __shfl_xor_sync(0xffffffffu, sq, 2);
            if (qlane == 0) part[row_l][warp_n] = make_float2(s, sq);
        }
    }
    __syncthreads();
    #pragma unroll
    for (int mt=0; mt<2; mt++) {
        #pragma unroll
        for (int half=0; half<2; half++) {
            int row_l = warp_m*32 + mt*16 + quad + half*8;
            int grow = m0 + row_l;
            float s = 0.f, sq = 0.f;
            #pragma unroll
            for (int w=0; w<4; w++) { float2 pp = part[row_l][w]; s += pp.x; sq += pp.y; }
            float mu = s * (1.0f/256.0f);
            float var = sq * (1.0f/256.0f) - mu*mu;
            float rstd = rsqrtf(var + 1e-5f);
            #pragma unroll
            for (int nt=0; nt<8; nt++) {
                int col = warp_n*64 + nt*8 + qlane*2;
                float2 gg = *(const float2*)(ln_g + col);
                float2 bb = *(const float2*)(ln_b + col);
                float y0 = acc[mt][nt][half*2+0];
                float y1 = acc[mt][nt][half*2+1];
                float2 o;
                o.x = (y0 - mu) * rstd * gg.x + bb.x;
                o.y = (y1 - mu) * rstd * gg.y + bb.y;
                *(float2*)(out + (size_t)grow*D_ + col) = o;
            }
        }
    }
}

// ---------------- launch ----------------
extern "C" void kernel_launch(void* const* d_in, const int* in_sizes, int n_in,
                              void* d_out, int out_size) {
    const float* node_embed = (const float*)d_in[0];
    const float* input_x    = (const float*)d_in[1];
    const int*   adj        = (const int*)  d_in[2];
    const float* WQi_w      = (const float*)d_in[3];
    const float* WQi_b      = (const float*)d_in[4];
    const float* WQ_w       = (const float*)d_in[5];
    const float* WQ_b       = (const float*)d_in[6];
    const float* WK_w       = (const float*)d_in[7];
    const float* WK_b       = (const float*)d_in[8];
    const float* WV_w       = (const float*)d_in[9];
    const float* WV_b       = (const float*)d_in[10];
    const float* WF_w       = (const float*)d_in[11];
    const float* WF_b       = (const float*)d_in[12];
    const float* ln_g       = (const float*)d_in[13];
    const float* ln_b       = (const float*)d_in[14];
    float* out = (float*)d_out;

    cudaFuncSetAttribute(k_attn, cudaFuncAttributeMaxDynamicSharedMemorySize, AT_TOT);

    k_x1      <<<B_, F_>>>(input_x, WQi_w, WQi_b);
    k_cvtw    <<<1216, 256>>>(WQ_w, WK_w, WV_w, WF_w);
    k_qkv16   <<<dim3(10, 128), 256>>>(node_embed, WQ_b, WK_b, WV_b);
    k_attn    <<<dim3(32, B_*R_), 256, AT_TOT>>>(adj);
    k_fused16 <<<M_TOT/64, 256>>>(node_embed, WF_b, ln_g, ln_b, out);
}